// round 15
// baseline (speedup 1.0000x reference)
#include <cuda_runtime.h>
#include <cuda_fp16.h>
#include <cstdint>

#define N_NODES 100000
#define D_IN    512
#define D_OUT   128
#define N_EDGES 640000

#define BM  128
#define BK  32
#define NIT (D_IN / BK)         // 16

// GEMM dynamic smem layout
#define SM_A16 0                // 2 x 8192 (fp16 swizzled tiles)
#define SM_B16 16384            // 2 x 8192
#define SM_A32 32768            // 3 x 16384 (fp32 A staging ring)
#define GEMM_SMEM (32768 + 3 * 16384)   // 81920 B

// Scratch (static device arrays: allocation-free)
__device__ __align__(16) __half g_h    [(size_t)N_NODES * D_OUT]; // h = X @ W (fp16)
__device__ __align__(16) __half g_Bt   [(size_t)D_OUT   * D_IN ]; // W^T as fp16
__device__ int  g_count [N_NODES];
__device__ int  g_offset[N_NODES];
__device__ int  g_rank  [N_EDGES];
__device__ int  g_total;
__device__ __align__(8) int2 g_edges[N_EDGES];   // (src, w-bits) bucketed by dst

// ---------------------------------------------------------------------------
// helpers
// ---------------------------------------------------------------------------
__device__ __forceinline__ void cp16(uint32_t saddr, const void* g) {
    asm volatile("cp.async.cg.shared.global [%0], [%1], 16;" :: "r"(saddr), "l"(g));
}
#define CP_COMMIT() asm volatile("cp.async.commit_group;" ::: "memory")
#define CP_WAIT1()  asm volatile("cp.async.wait_group 1;" ::: "memory")
#define CP_WAIT0()  asm volatile("cp.async.wait_group 0;" ::: "memory")

__device__ __forceinline__ uint32_t pack_half2(float lo, float hi) {
    uint32_t u;
    asm("cvt.rn.f16x2.f32 %0, %1, %2;" : "=r"(u) : "f"(hi), "f"(lo));
    return u;
}
__device__ __forceinline__ uint32_t soff(int row, int kc) {
    return (uint32_t)(row * 64 + ((kc ^ ((row >> 1) & 3)) << 4));
}
#define LDS128F(q, a) \
    asm volatile("ld.shared.v4.f32 {%0,%1,%2,%3}, [%4];" \
        : "=f"((q).x), "=f"((q).y), "=f"((q).z), "=f"((q).w) : "r"(a))
#define STS128(a, h0, h1, h2, h3) \
    asm volatile("st.shared.v4.b32 [%0], {%1,%2,%3,%4};" \
        :: "r"(a), "r"(h0), "r"(h1), "r"(h2), "r"(h3) : "memory")
#define LDM_X4(r, a) \
    asm volatile("ldmatrix.sync.aligned.m8n8.x4.shared.b16 {%0,%1,%2,%3}, [%4];" \
        : "=r"((r)[0]), "=r"((r)[1]), "=r"((r)[2]), "=r"((r)[3]) : "r"(a))
#define LDM_X2(r, a) \
    asm volatile("ldmatrix.sync.aligned.m8n8.x2.shared.b16 {%0,%1}, [%2];" \
        : "=r"((r)[0]), "=r"((r)[1]) : "r"(a))

__device__ __forceinline__ void mma16816(float c[4], const uint32_t a[4], const uint32_t b[2]) {
    asm volatile(
        "mma.sync.aligned.m16n8k16.row.col.f32.f16.f16.f32 "
        "{%0,%1,%2,%3}, {%4,%5,%6,%7}, {%8,%9}, {%0,%1,%2,%3};"
        : "+f"(c[0]), "+f"(c[1]), "+f"(c[2]), "+f"(c[3])
        : "r"(a[0]), "r"(a[1]), "r"(a[2]), "r"(a[3]), "r"(b[0]), "r"(b[1]));
}

// ---------------------------------------------------------------------------
// Kernel 0: g_Bt[n][k] = half(W[k][n])
// ---------------------------------------------------------------------------
__global__ void transposeW_kernel(const float* __restrict__ W) {
    __shared__ float tile[32][33];
    const int k0 = (blockIdx.x >> 2) * 32;
    const int n0 = (blockIdx.x & 3) * 32;
    const int r = threadIdx.x >> 5, c = threadIdx.x & 31;
#pragma unroll
    for (int i = 0; i < 32; i += 8)
        tile[r + i][c] = W[(size_t)(k0 + r + i) * D_OUT + n0 + c];
    __syncthreads();
#pragma unroll
    for (int i = 0; i < 32; i += 8)
        g_Bt[(size_t)(n0 + r + i) * D_IN + k0 + c] = __float2half_rn(tile[c][r + i]);
}

// ---------------------------------------------------------------------------
// CSR-bucket build: hist captures per-edge rank -> reorder needs NO atomics
// ---------------------------------------------------------------------------
__global__ void zero_kernel() {
    int i = blockIdx.x * blockDim.x + threadIdx.x;
    if (i < N_NODES) g_count[i] = 0;
    if (i == 0) g_total = 0;
}

__global__ void hist_kernel(const int* __restrict__ dst) {
    int e = blockIdx.x * blockDim.x + threadIdx.x;
    if (e < N_EDGES) g_rank[e] = atomicAdd(&g_count[dst[e]], 1);
}

__global__ void offsets_kernel() {
    __shared__ int warpsum[8];
    __shared__ int blockbase;
    const int n = blockIdx.x * 256 + threadIdx.x;
    const int lane = threadIdx.x & 31, wid = threadIdx.x >> 5;
    const int v = (n < N_NODES) ? g_count[n] : 0;

    int s = v;
#pragma unroll
    for (int d = 1; d < 32; d <<= 1) {
        int u = __shfl_up_sync(0xffffffffu, s, d);
        if (lane >= d) s += u;
    }
    if (lane == 31) warpsum[wid] = s;
    __syncthreads();
    if (wid == 0) {
        int ws = (lane < 8) ? warpsum[lane] : 0;
#pragma unroll
        for (int d = 1; d < 8; d <<= 1) {
            int u = __shfl_up_sync(0xffffffffu, ws, d);
            if (lane >= d) ws += u;
        }
        if (lane < 8) warpsum[lane] = ws;
        if (lane == 7) blockbase = atomicAdd(&g_total, ws);
    }
    __syncthreads();
    const int base = blockbase + (wid ? warpsum[wid - 1] : 0) + (s - v);
    if (n < N_NODES) g_offset[n] = base;
}

__global__ void reorder_kernel(const int* __restrict__ src,
                               const int* __restrict__ dst,
                               const float* __restrict__ ew) {
    int e = blockIdx.x * blockDim.x + threadIdx.x;
    if (e >= N_EDGES) return;
    int pos = g_offset[dst[e]] + g_rank[e];
    g_edges[pos] = make_int2(src[e], __float_as_int(ew[e]));
}

// ---------------------------------------------------------------------------
// fp16 GEMM  g_h = X @ W.
// R14: A streamed via cp.async fp32 ring (3 slots, issued 3 iters ahead) —
// in-flight A data lives in smem, not registers, so DRAM MLP is no longer
// capped by occupancy. Each thread converts exactly the chunks it copied
// (thread-private ring -> no barrier needed beyond wait_group).
// Group order per iter: commit [B(it+1)] then [A32(it+3)]; wait_group 1
// leaves only the newest A32 group in flight.
// ---------------------------------------------------------------------------
__global__ __launch_bounds__(256, 2)
void gemm_fp16_kernel(const float* __restrict__ A) {   // [N_NODES, 512] f32
    extern __shared__ __align__(16) uint8_t smem[];
    const uint32_t smb  = (uint32_t)__cvta_generic_to_shared(smem);
    const uint32_t sA16 = smb + SM_A16;
    const uint32_t sB16 = smb + SM_B16;
    const uint32_t sA32 = smb + SM_A32;

    const int t = threadIdx.x, warp = t >> 5, lane = t & 31;
    const int wm = (warp >> 2) * 64;
    const int wn = (warp & 3) * 32;
    const int blockRow = blockIdx.x * BM;

    const int fr  = t >> 2;                 // 0..63
    const int kc  = t & 3;                  // 16B chunk within 64B fp16 row
    int gr0 = blockRow + fr;       if (gr0 >= N_NODES) gr0 = N_NODES - 1;
    int gr1 = blockRow + fr + 64;  if (gr1 >= N_NODES) gr1 = N_NODES - 1;
    const float* pA0 = A + (size_t)gr0 * D_IN + kc * 8;
    const float* pA1 = A + (size_t)gr1 * D_IN + kc * 8;
    const __half* pB0 = g_Bt + (size_t)fr * D_IN + kc * 8;
    const __half* pB1 = g_Bt + (size_t)(fr + 64) * D_IN + kc * 8;
    const uint32_t offA0 = soff(fr, kc), offA1 = soff(fr + 64, kc);
    // thread-private chunk offsets within an A32 ring slot (row-major 128x128B)
    const uint32_t a32o0 = (uint32_t)(fr * 128 + kc * 32);
    const uint32_t a32o1 = (uint32_t)((fr + 64) * 128 + kc * 32);

    // ---- prologue ----
    // B(0)  [group 0]
    cp16(sB16 + offA0, pB0);
    cp16(sB16 + offA1, pB1);
    CP_COMMIT();
    // A32(1) -> slot 1  [group 1]
    {
        uint32_t s = sA32 + 1 * 16384;
        cp16(s + a32o0,      pA0 + BK);  cp16(s + a32o0 + 16, pA0 + BK + 4);
        cp16(s + a32o1,      pA1 + BK);  cp16(s + a32o1 + 16, pA1 + BK + 4);
    }
    CP_COMMIT();
    // A32(2) -> slot 2  [group 2, stays in flight]
    {
        uint32_t s = sA32 + 2 * 16384;
        cp16(s + a32o0,      pA0 + 2 * BK);  cp16(s + a32o0 + 16, pA0 + 2 * BK + 4);
        cp16(s + a32o1,      pA1 + 2 * BK);  cp16(s + a32o1 + 16, pA1 + 2 * BK + 4);
    }
    CP_COMMIT();
    // A16(0): direct LDG fill (once)
    {
        float4 q0 = *(const float4*)(pA0 + 0), q1 = *(const float4*)(pA0 + 4);
        float4 q2 = *(const float4*)(pA1 + 0), q3 = *(const float4*)(pA1 + 4);
        STS128(sA16 + offA0, pack_half2(q0.x, q0.y), pack_half2(q0.z, q0.w),
                             pack_half2(q1.x, q1.y), pack_half2(q1.z, q1.w));
        STS128(sA16 + offA1, pack_half2(q2.x, q2.y), pack_half2(q2.z, q2.w),
                             pack_half2(q3.x, q3.y), pack_half2(q3.z, q3.w));
    }
    CP_WAIT1();          // B(0) + A32(1) complete; A32(2) flying
    __syncthreads();

    float acc[4][4][4] = {};

    for (int it = 0; it < NIT; ++it) {
        const uint32_t aB = sA16 + (uint32_t)((it & 1) << 13);
        const uint32_t bB = sB16 + (uint32_t)((it & 1) << 13);
        const uint32_t aN = sA16 + (uint32_t)(((it & 1) ^ 1) << 13);
        const uint32_t bN = sB16 + (uint32_t)(((it & 1) ^ 1) << 13);

        // ---- convert A16(it+1) from ring slot (it+1)%3 (own-thread data) ----
        if (it + 1 < NIT) {
            uint32_t s = sA32 + (uint32_t)(((it + 1) % 3) * 16384);
            float4 q0, q1, q2, q3;
            LDS128F(q0, s + a32o0); LDS128F(q1, s + a32o0 + 16);
            LDS128F(q2, s + a32o1); LDS128F(q3, s + a32o1 + 16);
            STS128(aN + offA0, pack_half2(q0.x, q0.y), pack_half2(q0.z, q0.w),
                               pack_half2(q1.x, q1.y), pack_half2(q1.z, q1.w));
            STS128(aN + offA1, pack_half2(q2.x, q2.y), pack_half2(q2.z, q2.w),
                               pack_half2(q3.x, q3.y), pack_half2(q3.z, q3.w));
            // B(it+1)
            const int ko = (it + 1) * BK;
            cp16(bN + offA0, pB0 + ko);
            cp16(bN + offA1, pB1 + ko);
        }
        CP_COMMIT();      // B group (possibly empty)
        // ---- A32(it+3) into ring slot (it+3)%3 ----
        if (it + 3 < NIT) {
            uint32_t s = sA32 + (uint32_t)(((it + 3) % 3) * 16384);
            const int ko = (it + 3) * BK;
            cp16(s + a32o0,      pA0 + ko);  cp16(s + a32o0 + 16, pA0 + ko + 4);
            cp16(s + a32o1,      pA1 + ko);  cp16(s + a32o1 + 16, pA1 + ko + 4);
        }
        CP_COMMIT();      // A group (possibly empty)

        // ---- compute on current stage: 2 k-steps of m16n8k16 ----
#pragma unroll
        for (int s = 0; s < 2; s++) {
            uint32_t af[4][4], bf[4][2];
            const int akc = s * 2 + (lane >> 4);
            const int arl = lane & 15;
#pragma unroll
            for (int mi = 0; mi < 4; mi++)
                LDM_X4(af[mi], aB + soff(wm + mi * 16 + arl, akc));
            const int bkc = s * 2 + ((lane >> 3) & 1);
            const int brl = lane & 7;
#pragma unroll
            for (int ni = 0; ni < 4; ni++)
                LDM_X2(bf[ni], bB + soff(wn + ni * 8 + brl, bkc));
#pragma unroll
            for (int mi = 0; mi < 4; mi++)
#pragma unroll
                for (int ni = 0; ni < 4; ni++)
                    mma16816(acc[mi][ni], af[mi], bf[ni]);
        }

        if (it + 1 < NIT) {
            CP_WAIT1();       // A32(it+2) + B(it+1) complete; newest A32 flying
            __syncthreads();
        }
    }

#pragma unroll
    for (int mi = 0; mi < 4; mi++) {
#pragma unroll
        for (int ni = 0; ni < 4; ni++) {
            int r0 = blockRow + wm + mi * 16 + (lane >> 2);
            int c0 = wn + ni * 8 + (lane & 3) * 2;
            if (r0 < N_NODES)
                *(uint32_t*)(g_h + (size_t)r0 * D_OUT + c0) =
                    pack_half2(acc[mi][ni][0], acc[mi][ni][1]);
            if (r0 + 8 < N_NODES)
                *(uint32_t*)(g_h + (size_t)(r0 + 8) * D_OUT + c0) =
                    pack_half2(acc[mi][ni][2], acc[mi][ni][3]);
        }
    }
}

// ---------------------------------------------------------------------------
// Aggregate (R7 version — measured fastest)
// ---------------------------------------------------------------------------
__global__ __launch_bounds__(256)
void aggregate_kernel(const float* __restrict__ bias, float* __restrict__ out) {
    const int w = (blockIdx.x * blockDim.x + threadIdx.x) >> 5;
    if (w >= N_NODES) return;
    const int lane = threadIdx.x & 31;
    const int off = g_offset[w];
    const int cnt = g_count[w];

    float a0 = 0.f, a1 = 0.f, a2 = 0.f, a3 = 0.f;

    for (int base = 0; base < cnt; base += 32) {
        const int nb = min(32, cnt - base);
        int2 e = (lane < nb) ? g_edges[off + base + lane] : make_int2(0, 0);
        for (int i = 0; i < nb; i++) {
            int   si = __shfl_sync(0xffffffffu, e.x, i);
            float wi = __int_as_float(__shfl_sync(0xffffffffu, e.y, i));
            uint2 raw = __ldg((const uint2*)(g_h + (size_t)si * D_OUT) + lane);
            float2 f01 = __half22float2(*(__half2*)&raw.x);
            float2 f23 = __half22float2(*(__half2*)&raw.y);
            a0 += wi * f01.x; a1 += wi * f01.y;
            a2 += wi * f23.x; a3 += wi * f23.y;
        }
    }

    float4 bv = ((const float4*)bias)[lane];
    ((float4*)out)[(size_t)w * 32 + lane] =
        make_float4(a0 + bv.x, a1 + bv.y, a2 + bv.z, a3 + bv.w);
}

// ---------------------------------------------------------------------------
extern "C" void kernel_launch(void* const* d_in, const int* in_sizes, int n_in,
                              void* d_out, int out_size) {
    const float* features = (const float*)d_in[0];  // [100000, 512] f32
    const int*   edge_src = (const int*)d_in[1];    // [640000] int32
    const int*   edge_dst = (const int*)d_in[2];    // [640000] int32
    const float* edge_w   = (const float*)d_in[3];  // [640000] f32
    const float* weights  = (const float*)d_in[4];  // [512, 128] f32
    const float* bias     = (const float*)d_in[5];  // [128] f32
    float* out = (float*)d_out;                     // [100000, 128] f32

    (void)in_sizes; (void)n_in; (void)out_size;

    // >48KB dynamic smem opt-in (idempotent, host-side, capture-safe)
    cudaFuncSetAttribute(gemm_fp16_kernel,
                         cudaFuncAttributeMaxDynamicSharedMemorySize, GEMM_SMEM);

    // GEMM kept at launch index 3 (the slot the ncu window profiles).
    transposeW_kernel<<<64, 256>>>(weights);                                    // 0
    zero_kernel<<<(N_NODES + 255) / 256, 256>>>();                              // 1
    hist_kernel<<<(N_EDGES + 255) / 256, 256>>>(edge_dst);                      // 2
    gemm_fp16_kernel<<<(N_NODES + BM - 1) / BM, 256, GEMM_SMEM>>>(features);    // 3 <- profiled
    offsets_kernel<<<(N_NODES + 255) / 256, 256>>>();                           // 4
    reorder_kernel<<<(N_EDGES + 255) / 256, 256>>>(edge_src, edge_dst, edge_w); // 5
    aggregate_kernel<<<(N_NODES * 32 + 255) / 256, 256>>>(bias, out);           // 6
}

// round 17
// speedup vs baseline: 1.0228x; 1.0228x over previous
#include <cuda_runtime.h>
#include <cuda_fp16.h>
#include <cstdint>

#define N_NODES 100000
#define D_IN    512
#define D_OUT   128
#define N_EDGES 640000

#define BM  128
#define BK  32
#define NIT (D_IN / BK)         // 16

#define GEMM_BLOCKS ((N_NODES + BM - 1) / BM)   // 782
#define HIST_BLOCKS (N_EDGES / 256)             // 2500
#define REORD_BLOCKS (N_EDGES / 256)            // 2500

// Scratch (static device arrays: allocation-free)
__device__ __align__(16) __half g_h    [(size_t)N_NODES * D_OUT]; // h = X @ W (fp16)
__device__ __align__(16) __half g_Bt   [(size_t)D_OUT   * D_IN ]; // W^T as fp16
__device__ int  g_count [N_NODES];
__device__ int  g_offset[N_NODES];
__device__ int  g_rank  [N_EDGES];
__device__ int  g_total;
__device__ __align__(8) int2 g_edges[N_EDGES];   // (src, w-bits) bucketed by dst

// ---------------------------------------------------------------------------
// helpers
// ---------------------------------------------------------------------------
__device__ __forceinline__ void cp16(uint32_t saddr, const void* g) {
    asm volatile("cp.async.cg.shared.global [%0], [%1], 16;" :: "r"(saddr), "l"(g));
}
__device__ __forceinline__ uint32_t pack_half2(float lo, float hi) {
    uint32_t u;
    asm("cvt.rn.f16x2.f32 %0, %1, %2;" : "=r"(u) : "f"(hi), "f"(lo));
    return u;
}
__device__ __forceinline__ uint32_t soff(int row, int kc) {
    return (uint32_t)(row * 64 + ((kc ^ ((row >> 1) & 3)) << 4));
}
#define LDM_X4(r, a) \
    asm volatile("ldmatrix.sync.aligned.m8n8.x4.shared.b16 {%0,%1,%2,%3}, [%4];" \
        : "=r"((r)[0]), "=r"((r)[1]), "=r"((r)[2]), "=r"((r)[3]) : "r"(a))
#define LDM_X2(r, a) \
    asm volatile("ldmatrix.sync.aligned.m8n8.x2.shared.b16 {%0,%1}, [%2];" \
        : "=r"((r)[0]), "=r"((r)[1]) : "r"(a))

__device__ __forceinline__ void mma16816(float c[4], const uint32_t a[4], const uint32_t b[2]) {
    asm volatile(
        "mma.sync.aligned.m16n8k16.row.col.f32.f16.f16.f32 "
        "{%0,%1,%2,%3}, {%4,%5,%6,%7}, {%8,%9}, {%0,%1,%2,%3};"
        : "+f"(c[0]), "+f"(c[1]), "+f"(c[2]), "+f"(c[3])
        : "r"(a[0]), "r"(a[1]), "r"(a[2]), "r"(a[3]), "r"(b[0]), "r"(b[1]));
}

// ---------------------------------------------------------------------------
// Prep kernel (launch 1): blocks [0,64) transpose W -> g_Bt (fp16);
// blocks [64, 64+2500) hist with rank capture. Independent writes.
// ---------------------------------------------------------------------------
__global__ void prep_kernel(const float* __restrict__ W, const int* __restrict__ dst) {
    __shared__ float tile[32][33];
    if (blockIdx.x < 64) {
        const int k0 = ((int)blockIdx.x >> 2) * 32;
        const int n0 = ((int)blockIdx.x & 3) * 32;
        const int r = threadIdx.x >> 5, c = threadIdx.x & 31;
#pragma unroll
        for (int i = 0; i < 32; i += 8)
            tile[r + i][c] = W[(size_t)(k0 + r + i) * D_OUT + n0 + c];
        __syncthreads();
#pragma unroll
        for (int i = 0; i < 32; i += 8)
            g_Bt[(size_t)(n0 + r + i) * D_IN + k0 + c] = __float2half_rn(tile[c][r + i]);
    } else {
        int e = ((int)blockIdx.x - 64) * 256 + threadIdx.x;
        if (e < N_EDGES) g_rank[e] = atomicAdd(&g_count[dst[e]], 1);
    }
}

// ---------------------------------------------------------------------------
// Offsets (launch 2): block-level scan, ONE global atomic per 256 nodes
// ---------------------------------------------------------------------------
__global__ void offsets_kernel() {
    __shared__ int warpsum[8];
    __shared__ int blockbase;
    const int n = blockIdx.x * 256 + threadIdx.x;
    const int lane = threadIdx.x & 31, wid = threadIdx.x >> 5;
    const int v = (n < N_NODES) ? g_count[n] : 0;

    int s = v;
#pragma unroll
    for (int d = 1; d < 32; d <<= 1) {
        int u = __shfl_up_sync(0xffffffffu, s, d);
        if (lane >= d) s += u;
    }
    if (lane == 31) warpsum[wid] = s;
    __syncthreads();
    if (wid == 0) {
        int ws = (lane < 8) ? warpsum[lane] : 0;
#pragma unroll
        for (int d = 1; d < 8; d <<= 1) {
            int u = __shfl_up_sync(0xffffffffu, ws, d);
            if (lane >= d) ws += u;
        }
        if (lane < 8) warpsum[lane] = ws;
        if (lane == 7) blockbase = atomicAdd(&g_total, ws);
    }
    __syncthreads();
    const int base = blockbase + (wid ? warpsum[wid - 1] : 0) + (s - v);
    if (n < N_NODES) g_offset[n] = base;
}

// ---------------------------------------------------------------------------
// GEMM + reorder (launch 3): blocks [0,782) run the R13 fp16 GEMM;
// blocks [782, 782+2500) run the atomic-free reorder (needs offsets, done).
// Reorder streams fill the GEMM's wave-tail bubbles; no atomics -> no L2
// contention mechanism (the thing that sank R8's stream overlap).
// ---------------------------------------------------------------------------
__global__ __launch_bounds__(256, 2)
void gemm_reorder_kernel(const float* __restrict__ A,
                         const int* __restrict__ src,
                         const int* __restrict__ dst,
                         const float* __restrict__ ew) {
    __shared__ __align__(16) uint8_t smem[4 * 8192];

    if (blockIdx.x >= GEMM_BLOCKS) {
        // ---- reorder path ----
        int e = ((int)blockIdx.x - GEMM_BLOCKS) * 256 + threadIdx.x;
        if (e < N_EDGES) {
            int pos = g_offset[dst[e]] + g_rank[e];
            g_edges[pos] = make_int2(src[e], __float_as_int(ew[e]));
        }
        return;
    }

    // ---- GEMM path (R13, byte-exact) ----
    const uint32_t smb = (uint32_t)__cvta_generic_to_shared(smem);
    const uint32_t sA0 = smb;
    const uint32_t sB0 = smb + 16384;

    const int t = threadIdx.x, warp = t >> 5, lane = t & 31;
    const int wm = (warp >> 2) * 64;
    const int wn = (warp & 3) * 32;
    const int blockRow = blockIdx.x * BM;

    const int fr  = t >> 2;
    const int kc  = t & 3;
    int gr0 = blockRow + fr;       if (gr0 >= N_NODES) gr0 = N_NODES - 1;
    int gr1 = blockRow + fr + 64;  if (gr1 >= N_NODES) gr1 = N_NODES - 1;
    const float* pA0 = A + (size_t)gr0 * D_IN + kc * 8;
    const float* pA1 = A + (size_t)gr1 * D_IN + kc * 8;
    const __half* pB0 = g_Bt + (size_t)fr * D_IN + kc * 8;
    const __half* pB1 = g_Bt + (size_t)(fr + 64) * D_IN + kc * 8;
    const uint32_t offA0 = soff(fr, kc), offA1 = soff(fr + 64, kc);

    float4 pf[4];

    {
        float4 q0 = *(const float4*)(pA0 + 0), q1 = *(const float4*)(pA0 + 4);
        float4 q2 = *(const float4*)(pA1 + 0), q3 = *(const float4*)(pA1 + 4);
        cp16(sB0 + offA0, pB0);
        cp16(sB0 + offA1, pB1);
        asm volatile("cp.async.commit_group;");
        uint32_t h0 = pack_half2(q0.x, q0.y), h1 = pack_half2(q0.z, q0.w);
        uint32_t h2 = pack_half2(q1.x, q1.y), h3 = pack_half2(q1.z, q1.w);
        asm volatile("st.shared.v4.b32 [%0], {%1,%2,%3,%4};"
                     :: "r"(sA0 + offA0), "r"(h0), "r"(h1), "r"(h2), "r"(h3) : "memory");
        h0 = pack_half2(q2.x, q2.y); h1 = pack_half2(q2.z, q2.w);
        h2 = pack_half2(q3.x, q3.y); h3 = pack_half2(q3.z, q3.w);
        asm volatile("st.shared.v4.b32 [%0], {%1,%2,%3,%4};"
                     :: "r"(sA0 + offA1), "r"(h0), "r"(h1), "r"(h2), "r"(h3) : "memory");
        pf[0] = *(const float4*)(pA0 + BK);  pf[1] = *(const float4*)(pA0 + BK + 4);
        pf[2] = *(const float4*)(pA1 + BK);  pf[3] = *(const float4*)(pA1 + BK + 4);
    }
    asm volatile("cp.async.wait_group 0;");
    __syncthreads();

    float acc[4][4][4] = {};

    for (int it = 0; it < NIT; ++it) {
        const uint32_t aB = sA0 + (uint32_t)((it & 1) << 13);
        const uint32_t bB = sB0 + (uint32_t)((it & 1) << 13);
        const uint32_t aN = sA0 + (uint32_t)(((it & 1) ^ 1) << 13);
        const uint32_t bN = sB0 + (uint32_t)(((it & 1) ^ 1) << 13);

        if (it + 1 < NIT) {
            uint32_t h0 = pack_half2(pf[0].x, pf[0].y), h1 = pack_half2(pf[0].z, pf[0].w);
            uint32_t h2 = pack_half2(pf[1].x, pf[1].y), h3 = pack_half2(pf[1].z, pf[1].w);
            asm volatile("st.shared.v4.b32 [%0], {%1,%2,%3,%4};"
                         :: "r"(aN + offA0), "r"(h0), "r"(h1), "r"(h2), "r"(h3) : "memory");
            h0 = pack_half2(pf[2].x, pf[2].y); h1 = pack_half2(pf[2].z, pf[2].w);
            h2 = pack_half2(pf[3].x, pf[3].y); h3 = pack_half2(pf[3].z, pf[3].w);
            asm volatile("st.shared.v4.b32 [%0], {%1,%2,%3,%4};"
                         :: "r"(aN + offA1), "r"(h0), "r"(h1), "r"(h2), "r"(h3) : "memory");
            const int ko = (it + 1) * BK;
            cp16(bN + offA0, pB0 + ko);
            cp16(bN + offA1, pB1 + ko);
            asm volatile("cp.async.commit_group;");
        }
        if (it + 2 < NIT) {
            const int ko = (it + 2) * BK;
            pf[0] = *(const float4*)(pA0 + ko);  pf[1] = *(const float4*)(pA0 + ko + 4);
            pf[2] = *(const float4*)(pA1 + ko);  pf[3] = *(const float4*)(pA1 + ko + 4);
        }

#pragma unroll
        for (int s = 0; s < 2; s++) {
            uint32_t af[4][4], bf[4][2];
            const int akc = s * 2 + (lane >> 4);
            const int arl = lane & 15;
#pragma unroll
            for (int mi = 0; mi < 4; mi++)
                LDM_X4(af[mi], aB + soff(wm + mi * 16 + arl, akc));
            const int bkc = s * 2 + ((lane >> 3) & 1);
            const int brl = lane & 7;
#pragma unroll
            for (int ni = 0; ni < 4; ni++)
                LDM_X2(bf[ni], bB + soff(wn + ni * 8 + brl, bkc));
#pragma unroll
            for (int mi = 0; mi < 4; mi++)
#pragma unroll
                for (int ni = 0; ni < 4; ni++)
                    mma16816(acc[mi][ni], af[mi], bf[ni]);
        }

        if (it + 1 < NIT) {
            asm volatile("cp.async.wait_group 0;");
            __syncthreads();
        }
    }

#pragma unroll
    for (int mi = 0; mi < 4; mi++) {
#pragma unroll
        for (int ni = 0; ni < 4; ni++) {
            int r0 = blockRow + wm + mi * 16 + (lane >> 2);
            int c0 = wn + ni * 8 + (lane & 3) * 2;
            if (r0 < N_NODES)
                *(uint32_t*)(g_h + (size_t)r0 * D_OUT + c0) =
                    pack_half2(acc[mi][ni][0], acc[mi][ni][1]);
            if (r0 + 8 < N_NODES)
                *(uint32_t*)(g_h + (size_t)(r0 + 8) * D_OUT + c0) =
                    pack_half2(acc[mi][ni][2], acc[mi][ni][3]);
        }
    }
}

// ---------------------------------------------------------------------------
// Aggregate (launch 4; R7 version — measured fastest)
// ---------------------------------------------------------------------------
__global__ __launch_bounds__(256)
void aggregate_kernel(const float* __restrict__ bias, float* __restrict__ out) {
    const int w = (blockIdx.x * blockDim.x + threadIdx.x) >> 5;
    if (w >= N_NODES) return;
    const int lane = threadIdx.x & 31;
    const int off = g_offset[w];
    const int cnt = g_count[w];

    float a0 = 0.f, a1 = 0.f, a2 = 0.f, a3 = 0.f;

    for (int base = 0; base < cnt; base += 32) {
        const int nb = min(32, cnt - base);
        int2 e = (lane < nb) ? g_edges[off + base + lane] : make_int2(0, 0);
        for (int i = 0; i < nb; i++) {
            int   si = __shfl_sync(0xffffffffu, e.x, i);
            float wi = __int_as_float(__shfl_sync(0xffffffffu, e.y, i));
            uint2 raw = __ldg((const uint2*)(g_h + (size_t)si * D_OUT) + lane);
            float2 f01 = __half22float2(*(__half2*)&raw.x);
            float2 f23 = __half22float2(*(__half2*)&raw.y);
            a0 += wi * f01.x; a1 += wi * f01.y;
            a2 += wi * f23.x; a3 += wi * f23.y;
        }
    }

    float4 bv = ((const float4*)bias)[lane];
    ((float4*)out)[(size_t)w * 32 + lane] =
        make_float4(a0 + bv.x, a1 + bv.y, a2 + bv.z, a3 + bv.w);
}

// ---------------------------------------------------------------------------
extern "C" void kernel_launch(void* const* d_in, const int* in_sizes, int n_in,
                              void* d_out, int out_size) {
    const float* features = (const float*)d_in[0];  // [100000, 512] f32
    const int*   edge_src = (const int*)d_in[1];    // [640000] int32
    const int*   edge_dst = (const int*)d_in[2];    // [640000] int32
    const float* edge_w   = (const float*)d_in[3];  // [640000] f32
    const float* weights  = (const float*)d_in[4];  // [512, 128] f32
    const float* bias     = (const float*)d_in[5];  // [128] f32
    float* out = (float*)d_out;                     // [100000, 128] f32

    (void)in_sizes; (void)n_in; (void)out_size;

    // Zero counters (graph-ordered memset nodes; replaces zero_kernel)
    void* p_count = nullptr; void* p_total = nullptr;
    cudaGetSymbolAddress(&p_count, g_count);
    cudaGetSymbolAddress(&p_total, g_total);
    cudaMemsetAsync(p_count, 0, N_NODES * sizeof(int), 0);
    cudaMemsetAsync(p_total, 0, sizeof(int), 0);

    // 1) transpose || hist (independent)
    prep_kernel<<<64 + HIST_BLOCKS, 256>>>(weights, edge_dst);
    // 2) offsets (needs hist)
    offsets_kernel<<<(N_NODES + 255) / 256, 256>>>();
    // 3) GEMM || reorder (gemm needs transpose; reorder needs offsets)
    gemm_reorder_kernel<<<GEMM_BLOCKS + REORD_BLOCKS, 256>>>(
        features, edge_src, edge_dst, edge_w);
    // 4) aggregate (needs gemm + reorder)
    aggregate_kernel<<<(N_NODES * 32 + 255) / 256, 256>>>(bias, out);
}